// round 16
// baseline (speedup 1.0000x reference)
#include <cuda_runtime.h>

// SoftDTW forward, B=128, N=M=512, gamma=1.
// S = exp(-R):  S[i][j] = exp(-D[i][j]) * (S[i-1][j-1] + S[i-1][j] + S[i][j-1])
// Final: R = -(ln S + Es*ln2), joint power-of-2 rescaling every 5 phases.
//
// One CTA per batch, 5 warps: 3 producers + 2 consumers (column split).
//   consumer C (warp 3+C) owns cols [256C, 256C+256); lane l owns 8 cols;
//   2 rows per step. Consumer0: lane l at step s does row-pair rp = s - l.
//   Consumer1: rp = s - 36 - l  (32 col-offset + LAG=4 slack steps).
//   Boundary col 255->256 via 64-entry smem mailbox: warp3 lane31 publishes
//   {o,m,h,tag} per step; entry u is written at warp3-step u+31 and consumed
//   at warp4-step u+36 -> 5 steps of slack, poll succeeds immediately.
//   producers: exp(-D) into two 44-slot rings; region0 block t+1 stored at
//   phase t, region1 block t-5 stored at phase t (covers consumer1's lag).
//   Rescale: joint max via smem, extra barrier only on t%5==4 phases; the 5
//   mailbox entries straddling a rescale get corrected by f_last.

namespace {
constexpr int BATCH  = 128;
constexpr int NR     = 512;
constexpr int MC     = 512;
constexpr int NRP    = 256;                    // row pairs
constexpr int KP     = 6;                      // steps per phase
constexpr int RS     = 44;                     // ring slots per region
constexpr int LS     = 20;                     // words per lane chunk (16 + pad)
constexpr int SLOTW  = 32 * LS;                // 640 words per slot
constexpr int SMEM_BYTES = 2 * RS * SLOTW * 4; // 225280
constexpr int LAG    = 4;
constexpr int STEPS  = NRP + 31 + 32 + LAG;    // 323
constexpr int NPHASE = 54;                     // even; covers 324 steps
constexpr unsigned FULL = 0xffffffffu;
}

__device__ __forceinline__ float4 exp4neg(float4 v) {
    float4 r;
    r.x = __expf(-v.x); r.y = __expf(-v.y);
    r.z = __expf(-v.z); r.w = __expf(-v.w);
    return r;
}
__device__ __forceinline__ void sts128v(unsigned a, float x, float y, float z, float w) {
    asm volatile("st.volatile.shared.v4.f32 [%0], {%1,%2,%3,%4};"
                 :: "r"(a), "f"(x), "f"(y), "f"(z), "f"(w));
}
__device__ __forceinline__ float4 lds128v(unsigned a) {
    float4 v;
    asm volatile("ld.volatile.shared.v4.f32 {%0,%1,%2,%3}, [%4];"
                 : "=f"(v.x), "=f"(v.y), "=f"(v.z), "=f"(v.w) : "r"(a));
    return v;
}

// ---------------- consumer ----------------
template <int C>
__device__ __forceinline__ void consumer_loop(
    const float* __restrict__ region, float* __restrict__ out, int b, int l,
    unsigned mb, volatile float* jm)
{
    float h[8];
    #pragma unroll
    for (int j = 0; j < 8; ++j) h[j] = 0.f;
    float o7 = 0.f, m7 = 0.f;          // boundary history (col +7): rows 2rp-1, 2rp
    int   Es = 0;
    float f_last = 1.f;
    constexpr int BASE = C ? (32 + LAG) : 0;   // 36 or 0
    const float* lane_base = region + l * LS;

    for (int t = 0; t < NPHASE; ++t) {
        __syncthreads();
        const bool steady = C ? (t >= 12 && t <= 47) : (t >= 6 && t <= 41);
        if (steady) {
            int slot = (KP * t - BASE) % RS;
            #pragma unroll
            for (int q = 0; q < KP; ++q) {
                const int s = KP * t + q;
                const float4* e4 = (const float4*)(lane_base + slot * SLOTW);
                const float4 A0 = e4[0], A1 = e4[1], B0 = e4[2], B1 = e4[3];
                const float y0 = __shfl_up_sync(FULL, o7,  1);
                const float y1 = __shfl_up_sync(FULL, m7,  1);
                const float y2 = __shfl_up_sync(FULL, h[7], 1);
                float z0, z1, z2;
                if (C == 1) {
                    const int u = s - BASE;                 // entry index
                    const unsigned a = mb + (unsigned)((u & 63) * 16);
                    float4 v = lds128v(a);
                    while (__float_as_int(v.w) != u) v = lds128v(a);
                    const float corr = ((t % 5) == 0 && q <= LAG) ? f_last : 1.f;
                    z0 = (l == 0) ? v.x * corr : y0;
                    z1 = (l == 0) ? v.y * corr : y1;
                    z2 = (l == 0) ? v.z * corr : y2;
                } else {
                    z0 = (l == 0) ? 0.f : y0;
                    z1 = (l == 0) ? 0.f : y1;
                    z2 = (l == 0) ? 0.f : y2;
                }
                const float ea[8] = { A0.x, A0.y, A0.z, A0.w, A1.x, A1.y, A1.z, A1.w };
                const float eb[8] = { B0.x, B0.y, B0.z, B0.w, B1.x, B1.y, B1.z, B1.w };
                float pa[8];
                pa[0] = ea[0] * (z0 + h[0]);
                #pragma unroll
                for (int j = 1; j < 8; ++j) pa[j] = ea[j] * (h[j - 1] + h[j]);
                float av[8];
                float c = z1;
                #pragma unroll
                for (int j = 0; j < 8; ++j) { c = fmaf(ea[j], c, pa[j]); av[j] = c; }
                float pb[8];
                pb[0] = eb[0] * (z1 + av[0]);
                #pragma unroll
                for (int j = 1; j < 8; ++j) pb[j] = eb[j] * (av[j - 1] + av[j]);
                const float o7n = h[7];
                float d = z2;
                #pragma unroll
                for (int j = 0; j < 8; ++j) { d = fmaf(eb[j], d, pb[j]); h[j] = d; }
                o7 = o7n; m7 = av[7];
                if (C == 0 && l == 31)
                    sts128v(mb + (unsigned)(((s - 31) & 63) * 16),
                            o7, m7, h[7], __int_as_float(s - 31));
                slot = (slot + 1 == RS) ? 0 : slot + 1;
            }
        } else {
            #pragma unroll
            for (int q = 0; q < KP; ++q) {
                const int s = KP * t + q;
                if (s < STEPS) {
                    const int u = s - BASE;            // warp-uniform
                    if (u >= 0) {
                        const int slot = u % RS;
                        const float4* e4 = (const float4*)(lane_base + slot * SLOTW);
                        const float4 A0 = e4[0], A1 = e4[1], B0 = e4[2], B1 = e4[3];
                        const float y0 = __shfl_up_sync(FULL, o7,  1);
                        const float y1 = __shfl_up_sync(FULL, m7,  1);
                        const float y2 = __shfl_up_sync(FULL, h[7], 1);
                        float z0, z1, z2;
                        if (C == 1) {
                            float4 v = make_float4(0.f, 0.f, 0.f, 0.f);
                            if (u < NRP) {
                                const unsigned a = mb + (unsigned)((u & 63) * 16);
                                v = lds128v(a);
                                while (__float_as_int(v.w) != u) v = lds128v(a);
                            }
                            const float corr = ((t % 5) == 0 && q <= LAG) ? f_last : 1.f;
                            z0 = (l == 0) ? v.x * corr : y0;
                            z1 = (l == 0) ? v.y * corr : y1;
                            z2 = (l == 0) ? v.z * corr : y2;
                        } else {
                            z0 = (l == 0) ? ((s == 0) ? 1.f : 0.f) : y0;  // corner
                            z1 = (l == 0) ? 0.f : y1;
                            z2 = (l == 0) ? 0.f : y2;
                        }
                        const bool act = (unsigned)(u - l) < (unsigned)NRP;
                        const float ea[8] = { A0.x, A0.y, A0.z, A0.w, A1.x, A1.y, A1.z, A1.w };
                        const float eb[8] = { B0.x, B0.y, B0.z, B0.w, B1.x, B1.y, B1.z, B1.w };
                        float pa[8];
                        pa[0] = ea[0] * (z0 + h[0]);
                        #pragma unroll
                        for (int j = 1; j < 8; ++j) pa[j] = ea[j] * (h[j - 1] + h[j]);
                        float av[8];
                        float c = z1;
                        #pragma unroll
                        for (int j = 0; j < 8; ++j) { c = fmaf(ea[j], c, pa[j]); av[j] = c; }
                        float pb[8];
                        pb[0] = eb[0] * (z1 + av[0]);
                        #pragma unroll
                        for (int j = 1; j < 8; ++j) pb[j] = eb[j] * (av[j - 1] + av[j]);
                        const float o7n = h[7];
                        float d = z2;
                        #pragma unroll
                        for (int j = 0; j < 8; ++j) {
                            d = fmaf(eb[j], d, pb[j]);
                            h[j] = act ? d : h[j];
                        }
                        o7 = act ? o7n   : o7;
                        m7 = act ? av[7] : m7;
                        if (C == 0 && l == 31 && (unsigned)(s - 31) < (unsigned)NRP)
                            sts128v(mb + (unsigned)(((s - 31) & 63) * 16),
                                    o7, m7, h[7], __int_as_float(s - 31));
                    }
                }
            }
        }
        // joint rescale every 5 phases (extra barrier only on those phases)
        if ((t % 5) == 4) {
            float mx = fmaxf(o7, m7);
            #pragma unroll
            for (int j = 0; j < 8; ++j) mx = fmaxf(mx, h[j]);
            #pragma unroll
            for (int o = 16; o; o >>= 1)
                mx = fmaxf(mx, __shfl_xor_sync(FULL, mx, o));
            if (l == 0) jm[C] = mx;
            __syncthreads();
            const float mm = fmaxf(jm[0], jm[1]);
            if (mm > 0.f) {
                const int   k = (__float_as_int(mm) >> 23) - 127;
                const float f = __int_as_float((127 - k) << 23);
                #pragma unroll
                for (int j = 0; j < 8; ++j) h[j] *= f;
                o7 *= f; m7 *= f;
                Es += k;
                f_last = f;
            } else f_last = 1.f;
        }
    }
    // cell (511,511): consumer 1, lane 31, pair 255 at step 322 -> h[7]
    if (C == 1 && l == 31)
        out[b] = -(logf(h[7]) + (float)Es * 0.69314718055994531f);
}

__global__ __launch_bounds__(160, 1)
void softdtw_fwd(const float* __restrict__ D, float* __restrict__ out) {
    extern __shared__ float sm[];
    __shared__ float4 mbox_s[64];
    __shared__ volatile float jm_s[2];

    const int b   = blockIdx.x;
    const int tid = threadIdx.x;
    const int w   = tid >> 5;
    const int l   = tid & 31;
    const float* __restrict__ Db = D + (size_t)b * NR * MC;
    const unsigned mb = (unsigned)__cvta_generic_to_shared(mbox_s);

    if (w < 3) {
        // ---------------- producers (warps 0,1,2) ----------------
        const float* G0 = Db + 8 * l;          // region0: cols 8l..8l+7
        const float* G1 = G0 + 256;            // region1: cols 256+8l..
        float* R0 = sm;
        float* R1 = sm + RS * SLOTW;

        auto load_blk = [&](const float* G, int k, float4* buf) {
            #pragma unroll
            for (int pp = 0; pp < 2; ++pp) {
                const int rp = KP * k + 2 * w + pp;
                if (rp < NRP) {
                    const float* r0 = G + (size_t)(2 * rp) * MC;
                    const float4* s0 = (const float4*)r0;
                    const float4* s1 = (const float4*)(r0 + MC);
                    buf[pp * 4 + 0] = s0[0]; buf[pp * 4 + 1] = s0[1];
                    buf[pp * 4 + 2] = s1[0]; buf[pp * 4 + 3] = s1[1];
                }
            }
        };
        auto store_blk = [&](float* R, int k, const float4* buf) {
            #pragma unroll
            for (int pp = 0; pp < 2; ++pp) {
                const int rp = KP * k + 2 * w + pp;
                if (rp < NRP) {
                    const int slot = (rp + l) % RS;
                    float4* dst = (float4*)(R + slot * SLOTW + l * LS);
                    dst[0] = exp4neg(buf[pp * 4 + 0]);
                    dst[1] = exp4neg(buf[pp * 4 + 1]);
                    dst[2] = exp4neg(buf[pp * 4 + 2]);
                    dst[3] = exp4neg(buf[pp * 4 + 3]);
                }
            }
        };

        float4 X0[2][8], X1[2][8];
        {   // prologue: region0 block 0 stored before first barrier
            float4 T[8];
            load_blk(G0, 0, T);
            store_blk(R0, 0, T);
        }
        load_blk(G0, 1, X0[1]);   // region0 blocks 1,2
        load_blk(G0, 2, X0[0]);
        load_blk(G1, 0, X1[0]);   // region1 blocks 0,1 (stored at phases 5,6)
        load_blk(G1, 1, X1[1]);

        for (int t = 0; t < NPHASE; ++t) {
            __syncthreads();
            // region0: store block t+1, then refill same buffer with block t+3
            const int k0 = t + 1;
            if (k0 <= 42) store_blk(R0, k0, X0[k0 & 1]);
            const int k0f = t + 3;
            if (k0f <= 42) load_blk(G0, k0f, X0[k0f & 1]);   // same parity as k0
            // region1: store block t-5, refill with block t-3
            const int k1 = t - 5;
            if (k1 >= 0 && k1 <= 42) store_blk(R1, k1, X1[k1 & 1]);
            const int k1f = t - 3;
            if (k1f >= 0 && k1f <= 42) load_blk(G1, k1f, X1[k1f & 1]);
            if ((t % 5) == 4) __syncthreads();               // match rescale barrier
        }
    } else if (w == 3) {
        // init mailbox tags before first barrier
        #pragma unroll
        for (int i = 0; i < 2; ++i)
            sts128v(mb + (unsigned)((l + 32 * i) * 16), 0.f, 0.f, 0.f,
                    __int_as_float(-1));
        consumer_loop<0>(sm, out, b, l, mb, jm_s);
    } else {
        consumer_loop<1>(sm + RS * SLOTW, out, b, l, mb, jm_s);
    }
}

extern "C" void kernel_launch(void* const* d_in, const int* in_sizes, int n_in,
                              void* d_out, int out_size) {
    (void)in_sizes; (void)n_in; (void)out_size;
    const float* D = (const float*)d_in[0];
    float* o       = (float*)d_out;
    cudaFuncSetAttribute(softdtw_fwd, cudaFuncAttributeMaxDynamicSharedMemorySize, SMEM_BYTES);
    softdtw_fwd<<<BATCH, 160, SMEM_BYTES>>>(D, o);
}